// round 3
// baseline (speedup 1.0000x reference)
#include <cuda_runtime.h>
#include <math.h>

#define BSZ 2
#define SEQ 1024
#define TXT 512
#define DIMM 1536
#define NH 12
#define HDD 128
#define NKV 4
#define JD 3584
#define NE 16
#define NI 1344
#define CAP 512
#define LTOT 1536      // SEQ + TXT
#define NTOK 2048      // BSZ*SEQ
#define MROWS 16384    // NE*BSZ*CAP
#define IKV 512        // NKV*HDD
#define REP 3          // NH/NKV
#define EPSL 1e-6f

// ------------------------- scratch (device globals) -------------------------
__device__ float g_scale1[BSZ*DIMM];
__device__ float g_tg1[BSZ*DIMM];
__device__ float g_scale2[BSZ*DIMM];
__device__ float g_tg2[BSZ*DIMM];
__device__ float g_ctx[BSZ*TXT*DIMM];
__device__ float g_imgmod[NTOK*DIMM];
__device__ float g_q[NTOK*DIMM];
__device__ float g_kimg[NTOK*IKV];
__device__ float g_vimg[NTOK*IKV];
__device__ float g_ktxt[BSZ*TXT*IKV];
__device__ float g_vtxt[BSZ*TXT*IKV];
__device__ float g_k[BSZ*NKV*LTOT*HDD];
__device__ float g_v[BSZ*NKV*LTOT*HDD];
__device__ float g_attn[NTOK*DIMM];
__device__ float g_hs1[NTOK*DIMM];
__device__ float g_normed2[NTOK*DIMM];
__device__ float g_mod2[NTOK*DIMM];
__device__ float g_tembdot[BSZ*NE];
__device__ float g_aff[BSZ*NE*SEQ];
__device__ int   g_topidx[BSZ*NE*CAP];
__device__ float g_gating[BSZ*NE*CAP];
__device__ float g_sums[NTOK];
__device__ int   g_rowmap[MROWS];
__device__ float g_rscale[MROWS];
__device__ float g_routed[MROWS*DIMM];
__device__ float g_hmoe[MROWS*2*NI];
__device__ float g_actmoe[MROWS*NI];
__device__ float g_hsh[NTOK*2*NI];
__device__ float g_actsh[NTOK*NI];
__device__ float g_outflat[NTOK*DIMM];

// ------------------------- modulation: mod = silu(temb) @ W_mod^T + b -------
__global__ __launch_bounds__(256) void mod_kernel(const float* __restrict__ temb,
                                                  const float* __restrict__ Wm,
                                                  const float* __restrict__ bm) {
    int gw = (blockIdx.x * blockDim.x + threadIdx.x) >> 5;
    int lane = threadIdx.x & 31;
    if (gw >= BSZ * 4 * DIMM) return;
    int b = gw / (4 * DIMM);
    int j = gw - b * 4 * DIMM;
    const float* t = temb + b * DIMM;
    const float* w = Wm + (size_t)j * DIMM;
    float acc = 0.f;
    for (int kk = lane; kk < DIMM; kk += 32) {
        float x = t[kk];
        acc += (x / (1.f + __expf(-x))) * w[kk];
    }
    #pragma unroll
    for (int o = 16; o; o >>= 1) acc += __shfl_xor_sync(0xffffffffu, acc, o);
    if (lane == 0) {
        acc += bm[j];
        int q = j / DIMM, c = j - q * DIMM;
        if (q == 0)      g_scale1[b*DIMM + c] = 1.f + acc;
        else if (q == 1) g_tg1[b*DIMM + c]    = tanhf(fminf(fmaxf(acc, -2.f), 2.f));
        else if (q == 2) g_scale2[b*DIMM + c] = 1.f + acc;
        else             g_tg2[b*DIMM + c]    = tanhf(fminf(fmaxf(acc, -2.f), 2.f));
    }
}

// ------------------------- generic NT SGEMM ---------------------------------
// C[M,N] = A[M,K] * B[N,K]^T.  M,N multiples of 128; K multiple of 16.
// EPI 0: store   1: +bias[n]   2: C = resid + gate[b][n]*acc   3: atomic scatter
template<int EPI>
__global__ __launch_bounds__(256) void gemm_nt(
    const float* __restrict__ A, const float* __restrict__ B, float* __restrict__ C,
    int M, int N, int K,
    long long sA, long long sB, long long sC,
    const float* __restrict__ bias,
    const float* __restrict__ resid, const float* __restrict__ gate,
    const int* __restrict__ rowmap, const float* __restrict__ rscale)
{
    __shared__ float As[16][132];
    __shared__ float Bs[16][132];
    const int z = blockIdx.z;
    A += (long long)z * sA;
    B += (long long)z * sB;
    const int tid = threadIdx.x;
    const int m0 = blockIdx.y * 128, n0 = blockIdx.x * 128;
    const int ty = tid >> 4, tx = tid & 15;
    const int row = ty * 8, col = tx * 8;
    float acc[8][8];
    #pragma unroll
    for (int i = 0; i < 8; i++)
        #pragma unroll
        for (int j = 0; j < 8; j++) acc[i][j] = 0.f;

    for (int k0 = 0; k0 < K; k0 += 16) {
        #pragma unroll
        for (int i = 0; i < 2; i++) {
            int id = (tid << 1) + i;
            int r = id >> 2, c = (id & 3) << 2;
            float4 va = *(const float4*)(A + (long long)(m0 + r) * K + (k0 + c));
            As[c][r] = va.x; As[c+1][r] = va.y; As[c+2][r] = va.z; As[c+3][r] = va.w;
            float4 vb = *(const float4*)(B + (long long)(n0 + r) * K + (k0 + c));
            Bs[c][r] = vb.x; Bs[c+1][r] = vb.y; Bs[c+2][r] = vb.z; Bs[c+3][r] = vb.w;
        }
        __syncthreads();
        #pragma unroll
        for (int kk = 0; kk < 16; kk++) {
            float a[8], bb[8];
            *(float4*)(a)    = *(const float4*)&As[kk][row];
            *(float4*)(a+4)  = *(const float4*)&As[kk][row+4];
            *(float4*)(bb)   = *(const float4*)&Bs[kk][col];
            *(float4*)(bb+4) = *(const float4*)&Bs[kk][col+4];
            #pragma unroll
            for (int i = 0; i < 8; i++)
                #pragma unroll
                for (int j = 0; j < 8; j++) acc[i][j] += a[i] * bb[j];
        }
        __syncthreads();
    }

    if (EPI == 3) {
        #pragma unroll
        for (int i = 0; i < 8; i++) {
            int gr = z * M + m0 + row + i;
            int trow = rowmap[gr];
            float s = rscale[gr];
            float* cp = C + (long long)trow * N + n0 + col;
            #pragma unroll
            for (int j = 0; j < 8; j++) atomicAdd(&cp[j], acc[i][j] * s);
        }
    } else {
        float* Cz = C + (long long)z * sC;
        #pragma unroll
        for (int i = 0; i < 8; i++) {
            int m = m0 + row + i;
            long long off = (long long)m * N + n0 + col;
            float v[8];
            #pragma unroll
            for (int j = 0; j < 8; j++) {
                float x = acc[i][j];
                if (EPI == 1) x += bias[n0 + col + j];
                if (EPI == 2) x = resid[off + j] + gate[(m / SEQ) * N + n0 + col + j] * x;
                v[j] = x;
            }
            *(float4*)(Cz + off)     = *(float4*)(v);
            *(float4*)(Cz + off + 4) = *(float4*)(v + 4);
        }
    }
}

// ------------------------- LayerNorm (+ scale, optional normed out) ---------
__global__ __launch_bounds__(256) void ln_mod_kernel(const float* __restrict__ in,
                                                     const float* __restrict__ scale,
                                                     float* __restrict__ outmod,
                                                     float* __restrict__ outnorm) {
    int rowi = blockIdx.x;
    int b = rowi >> 10;
    const float* x = in + (size_t)rowi * DIMM;
    float s = 0.f, sq = 0.f;
    for (int d = threadIdx.x; d < DIMM; d += 256) { float v = x[d]; s += v; sq += v * v; }
    #pragma unroll
    for (int o = 16; o; o >>= 1) {
        s  += __shfl_xor_sync(0xffffffffu, s,  o);
        sq += __shfl_xor_sync(0xffffffffu, sq, o);
    }
    __shared__ float rs[8], rq[8], mv[2];
    int w = threadIdx.x >> 5;
    if ((threadIdx.x & 31) == 0) { rs[w] = s; rq[w] = sq; }
    __syncthreads();
    if (threadIdx.x == 0) {
        float S = 0.f, Q = 0.f;
        for (int i = 0; i < 8; i++) { S += rs[i]; Q += rq[i]; }
        float mean = S / DIMM;
        float var = Q / DIMM - mean * mean;
        mv[0] = mean; mv[1] = rsqrtf(var + EPSL);
    }
    __syncthreads();
    float mean = mv[0], rstd = mv[1];
    const float* sc = scale + (size_t)b * DIMM;
    for (int d = threadIdx.x; d < DIMM; d += 256) {
        float n = (x[d] - mean) * rstd;
        if (outnorm) outnorm[(size_t)rowi * DIMM + d] = n;
        outmod[(size_t)rowi * DIMM + d] = n * sc[d];
    }
}

// ------------------------- per-head RMSNorm of Q ----------------------------
__global__ __launch_bounds__(256) void rms_q_kernel(const float* __restrict__ w) {
    int gw = (blockIdx.x * blockDim.x + threadIdx.x) >> 5;
    if (gw >= NTOK * NH) return;
    int lane = threadIdx.x & 31;
    float* p = g_q + (size_t)gw * HDD;
    int d4 = lane << 2;
    float4 v = *(float4*)(p + d4);
    float ss = v.x*v.x + v.y*v.y + v.z*v.z + v.w*v.w;
    #pragma unroll
    for (int o = 16; o; o >>= 1) ss += __shfl_xor_sync(0xffffffffu, ss, o);
    float r = rsqrtf(ss / HDD + EPSL);
    float4 wv = *(const float4*)(w + d4);
    v.x *= r * wv.x; v.y *= r * wv.y; v.z *= r * wv.z; v.w *= r * wv.w;
    *(float4*)(p + d4) = v;
}

// ------------------------- K RMS + K/V repack to [b][kv][L][hd] -------------
__global__ __launch_bounds__(256) void kv_repack_kernel(const float* __restrict__ nk,
                                                        const float* __restrict__ nak) {
    int gw = (blockIdx.x * blockDim.x + threadIdx.x) >> 5;
    if (gw >= BSZ * NKV * LTOT) return;
    int lane = threadIdx.x & 31;
    int l = gw % LTOT;
    int bk = gw / LTOT;
    int kv = bk % NKV, b = bk / NKV;
    const float *ksrc, *vsrc, *w;
    if (l < SEQ) {
        ksrc = g_kimg + (size_t)(b * SEQ + l) * IKV + kv * HDD;
        vsrc = g_vimg + (size_t)(b * SEQ + l) * IKV + kv * HDD;
        w = nk;
    } else {
        int tt = l - SEQ;
        ksrc = g_ktxt + (size_t)(b * TXT + tt) * IKV + kv * HDD;
        vsrc = g_vtxt + (size_t)(b * TXT + tt) * IKV + kv * HDD;
        w = nak;
    }
    int d4 = lane << 2;
    float4 kvv = *(const float4*)(ksrc + d4);
    float ss = kvv.x*kvv.x + kvv.y*kvv.y + kvv.z*kvv.z + kvv.w*kvv.w;
    #pragma unroll
    for (int o = 16; o; o >>= 1) ss += __shfl_xor_sync(0xffffffffu, ss, o);
    float r = rsqrtf(ss / HDD + EPSL);
    float4 wv = *(const float4*)(w + d4);
    kvv.x *= r * wv.x; kvv.y *= r * wv.y; kvv.z *= r * wv.z; kvv.w *= r * wv.w;
    size_t dst = ((size_t)(b * NKV + kv) * LTOT + l) * HDD + d4;
    *(float4*)(g_k + dst) = kvv;
    *(float4*)(g_v + dst) = *(const float4*)(vsrc + d4);
}

// ------------------------- flash attention ----------------------------------
__global__ __launch_bounds__(256) void flash_kernel() {
    __shared__ float Qs[32][129];
    __shared__ float KVs[32][129];
    __shared__ float Ss[32][33];
    const int q0 = blockIdx.x * 32;
    const int h = blockIdx.y;
    const int b = blockIdx.z;
    const int kv = h / REP;
    const int t = threadIdx.x;
    for (int idx = t; idx < 1024; idx += 256) {
        int qi = idx >> 5, d4 = (idx & 31) << 2;
        float4 v = *(const float4*)(g_q + (size_t)(b * SEQ + q0 + qi) * DIMM + h * HDD + d4);
        Qs[qi][d4] = v.x; Qs[qi][d4+1] = v.y; Qs[qi][d4+2] = v.z; Qs[qi][d4+3] = v.w;
    }
    const int q = t >> 3, dg = t & 7;
    float acc[16];
    #pragma unroll
    for (int i = 0; i < 16; i++) acc[i] = 0.f;
    float m = -1e30f, l = 0.f;
    const float sc = 0.08838834764831845f;  // 1/sqrt(128)
    const float* kbase = g_k + (size_t)(b * NKV + kv) * LTOT * HDD;
    const float* vbase = g_v + (size_t)(b * NKV + kv) * LTOT * HDD;
    __syncthreads();
    for (int k0 = 0; k0 < LTOT; k0 += 32) {
        for (int idx = t; idx < 1024; idx += 256) {
            int ki = idx >> 5, d4 = (idx & 31) << 2;
            float4 v = *(const float4*)(kbase + (size_t)(k0 + ki) * HDD + d4);
            KVs[ki][d4] = v.x; KVs[ki][d4+1] = v.y; KVs[ki][d4+2] = v.z; KVs[ki][d4+3] = v.w;
        }
        __syncthreads();
        {
            int kb = dg << 2;
            float s0 = 0.f, s1 = 0.f, s2 = 0.f, s3 = 0.f;
            #pragma unroll 4
            for (int d = 0; d < 128; d++) {
                float qv = Qs[q][d];
                s0 += qv * KVs[kb][d];
                s1 += qv * KVs[kb+1][d];
                s2 += qv * KVs[kb+2][d];
                s3 += qv * KVs[kb+3][d];
            }
            Ss[q][kb] = s0 * sc; Ss[q][kb+1] = s1 * sc;
            Ss[q][kb+2] = s2 * sc; Ss[q][kb+3] = s3 * sc;
        }
        __syncthreads();
        float srow[32];
        float rmax = -1e30f;
        #pragma unroll
        for (int k = 0; k < 32; k++) { srow[k] = Ss[q][k]; rmax = fmaxf(rmax, srow[k]); }
        // load V into KVs (K reads finished at previous sync)
        for (int idx = t; idx < 1024; idx += 256) {
            int ki = idx >> 5, d4 = (idx & 31) << 2;
            float4 v = *(const float4*)(vbase + (size_t)(k0 + ki) * HDD + d4);
            KVs[ki][d4] = v.x; KVs[ki][d4+1] = v.y; KVs[ki][d4+2] = v.z; KVs[ki][d4+3] = v.w;
        }
        float newm = fmaxf(m, rmax);
        float corr = __expf(m - newm);
        float psum = 0.f;
        #pragma unroll
        for (int k = 0; k < 32; k++) { srow[k] = __expf(srow[k] - newm); psum += srow[k]; }
        l = l * corr + psum;
        m = newm;
        #pragma unroll
        for (int i = 0; i < 16; i++) acc[i] *= corr;
        __syncthreads();
        #pragma unroll
        for (int k = 0; k < 32; k++) {
            float p = srow[k];
            #pragma unroll
            for (int i = 0; i < 16; i++) acc[i] += p * KVs[k][dg + (i << 3)];
        }
        __syncthreads();
    }
    float inv = 1.f / l;
    float* op = g_attn + (size_t)(b * SEQ + q0 + q) * DIMM + h * HDD;
    #pragma unroll
    for (int i = 0; i < 16; i++) op[dg + (i << 3)] = acc[i] * inv;
}

// ------------------------- router ------------------------------------------
__global__ __launch_bounds__(1024) void tembdot_kernel(const float* __restrict__ temb,
                                                       const float* __restrict__ Wg) {
    int wid = threadIdx.x >> 5, lane = threadIdx.x & 31;
    int b = wid / NE, e = wid % NE;
    const float* t = temb + b * DIMM;
    const float* w = Wg + (size_t)e * 2 * DIMM;
    float acc = 0.f;
    for (int d = lane; d < DIMM; d += 32) acc += t[d] * w[d];
    #pragma unroll
    for (int o = 16; o; o >>= 1) acc += __shfl_xor_sync(0xffffffffu, acc, o);
    if (lane == 0) g_tembdot[wid] = acc;
}

__global__ __launch_bounds__(128) void router_kernel(const float* __restrict__ Wg) {
    __shared__ float lg[NE];
    int tokid = blockIdx.x;
    int b = tokid >> 10, s = tokid & 1023;
    int w = threadIdx.x >> 5, lane = threadIdx.x & 31;
    const float* x = g_normed2 + (size_t)tokid * DIMM;
    for (int e = w * 4; e < w * 4 + 4; e++) {
        const float* wg = Wg + (size_t)e * 2 * DIMM + DIMM;
        float acc = 0.f;
        for (int d = lane; d < DIMM; d += 32) acc += x[d] * wg[d];
        #pragma unroll
        for (int o = 16; o; o >>= 1) acc += __shfl_xor_sync(0xffffffffu, acc, o);
        if (lane == 0) lg[e] = acc + g_tembdot[b * NE + e];
    }
    __syncthreads();
    if (threadIdx.x == 0) {
        float mx = -1e30f;
        for (int e = 0; e < NE; e++) mx = fmaxf(mx, lg[e]);
        float ex[NE], sm = 0.f;
        for (int e = 0; e < NE; e++) { ex[e] = __expf(lg[e] - mx); sm += ex[e]; }
        float inv = 1.f / sm;
        for (int e = 0; e < NE; e++)
            g_aff[((size_t)(b * NE + e)) * SEQ + s] = ex[e] * inv;
    }
}

// ------------------------- exact top-k via bitonic sort ---------------------
__global__ __launch_bounds__(512) void topk_kernel() {
    __shared__ float v[1024];
    __shared__ int   id[1024];
    int be = blockIdx.x;
    const float* rowp = g_aff + (size_t)be * SEQ;
    int t = threadIdx.x;
    for (int i = t; i < 1024; i += 512) { v[i] = rowp[i]; id[i] = i; }
    __syncthreads();
    for (int k = 2; k <= 1024; k <<= 1) {
        for (int j = k >> 1; j > 0; j >>= 1) {
            for (int i = t; i < 1024; i += 512) {
                int ixj = i ^ j;
                if (ixj > i) {
                    bool up = ((i & k) == 0);
                    float va = v[i], vb = v[ixj];
                    int ia = id[i], ib = id[ixj];
                    bool a_first = (va > vb) || (va == vb && ia < ib);
                    bool sw = up ? !a_first : a_first;
                    if (sw) { v[i] = vb; v[ixj] = va; id[i] = ib; id[ixj] = ia; }
                }
            }
            __syncthreads();
        }
    }
    if (t < CAP) {
        g_gating[be * CAP + t] = v[t];
        g_topidx[be * CAP + t] = id[t];
    }
}

__global__ void zero_sums_kernel() {
    int i = blockIdx.x * blockDim.x + threadIdx.x;
    if (i < NTOK) g_sums[i] = 0.f;
}

__global__ void sum_acc_kernel() {
    int i = blockIdx.x * blockDim.x + threadIdx.x;
    if (i >= BSZ * NE * CAP) return;
    int be = i / CAP;
    int b = be / NE;
    int tok = b * SEQ + g_topidx[i];
    atomicAdd(&g_sums[tok], g_gating[i]);
}

__global__ void gate_norm_kernel() {
    int i = blockIdx.x * blockDim.x + threadIdx.x;
    if (i >= BSZ * NE * CAP) return;
    int c = i % CAP;
    int be = i / CAP;
    int b = be / NE, e = be % NE;
    int tok = b * SEQ + g_topidx[i];
    float g = g_gating[i] / (g_sums[tok] + 1e-12f) * 2.5f;
    int rowflat = (e * BSZ + b) * CAP + c;
    g_rowmap[rowflat] = tok;
    g_rscale[rowflat] = g;
}

__global__ __launch_bounds__(256) void gather_kernel() {
    int r = blockIdx.x;
    int src = g_rowmap[r];
    const float4* s = (const float4*)(g_mod2 + (size_t)src * DIMM);
    float4* d = (float4*)(g_routed + (size_t)r * DIMM);
    for (int i = threadIdx.x; i < DIMM / 4; i += 256) d[i] = s[i];
}

// ------------------------- swiglu activation --------------------------------
__global__ __launch_bounds__(256) void swiglu_kernel(const float* __restrict__ h,
                                                     float* __restrict__ out) {
    int r = blockIdx.x;
    const float4* a = (const float4*)(h + (size_t)r * 2 * NI);
    const float4* g = (const float4*)(h + (size_t)r * 2 * NI + NI);
    float4* o = (float4*)(out + (size_t)r * NI);
    for (int i = threadIdx.x; i < NI / 4; i += 256) {
        float4 av = a[i], gv = g[i], ov;
        ov.x = av.x * (gv.x / (1.f + __expf(-gv.x)));
        ov.y = av.y * (gv.y / (1.f + __expf(-gv.y)));
        ov.z = av.z * (gv.z / (1.f + __expf(-gv.z)));
        ov.w = av.w * (gv.w / (1.f + __expf(-gv.w)));
        o[i] = ov;
    }
}

// ------------------------- final residual -----------------------------------
__global__ __launch_bounds__(256) void final_kernel(float* __restrict__ out) {
    int r = blockIdx.x;
    int b = r >> 10;
    const float4* hs = (const float4*)(g_hs1 + (size_t)r * DIMM);
    const float4* mo = (const float4*)(g_outflat + (size_t)r * DIMM);
    const float4* gg = (const float4*)(g_tg2 + (size_t)b * DIMM);
    float4* o = (float4*)(out + (size_t)r * DIMM);
    for (int i = threadIdx.x; i < DIMM / 4; i += 256) {
        float4 h = hs[i], m = mo[i], g = gg[i], v;
        v.x = h.x + g.x * m.x; v.y = h.y + g.y * m.y;
        v.z = h.z + g.z * m.z; v.w = h.w + g.w * m.w;
        o[i] = v;
    }
}

// ------------------------- launcher -----------------------------------------
extern "C" void kernel_launch(void* const* d_in, const int* in_sizes, int n_in,
                              void* d_out, int out_size) {
    const float* hidden = (const float*)d_in[0];
    const float* enc    = (const float*)d_in[1];
    const float* temb   = (const float*)d_in[2];
    const float* W_mod  = (const float*)d_in[3];
    const float* b_mod  = (const float*)d_in[4];
    const float* W_enc  = (const float*)d_in[5];
    const float* b_enc  = (const float*)d_in[6];
    const float* Wq     = (const float*)d_in[7];
    const float* Wk     = (const float*)d_in[8];
    const float* Wv     = (const float*)d_in[9];
    const float* Wak    = (const float*)d_in[10];
    const float* Wav    = (const float*)d_in[11];
    const float* nq_w   = (const float*)d_in[12];
    const float* nk_w   = (const float*)d_in[13];
    const float* nak_w  = (const float*)d_in[14];
    const float* Wo     = (const float*)d_in[15];
    const float* Wg     = (const float*)d_in[16];
    const float* We_in  = (const float*)d_in[17];
    const float* We_out = (const float*)d_in[18];
    const float* Ws_in  = (const float*)d_in[19];
    const float* Ws_out = (const float*)d_in[20];
    float* out = (float*)d_out;

    void* pv;
    cudaGetSymbolAddress(&pv, g_ctx);     float* p_ctx     = (float*)pv;
    cudaGetSymbolAddress(&pv, g_imgmod);  float* p_imgmod  = (float*)pv;
    cudaGetSymbolAddress(&pv, g_q);       float* p_q       = (float*)pv;
    cudaGetSymbolAddress(&pv, g_kimg);    float* p_kimg    = (float*)pv;
    cudaGetSymbolAddress(&pv, g_vimg);    float* p_vimg    = (float*)pv;
    cudaGetSymbolAddress(&pv, g_ktxt);    float* p_ktxt    = (float*)pv;
    cudaGetSymbolAddress(&pv, g_vtxt);    float* p_vtxt    = (float*)pv;
    cudaGetSymbolAddress(&pv, g_attn);    float* p_attn    = (float*)pv;
    cudaGetSymbolAddress(&pv, g_hs1);     float* p_hs1     = (float*)pv;
    cudaGetSymbolAddress(&pv, g_normed2); float* p_normed2 = (float*)pv;
    cudaGetSymbolAddress(&pv, g_mod2);    float* p_mod2    = (float*)pv;
    cudaGetSymbolAddress(&pv, g_routed);  float* p_routed  = (float*)pv;
    cudaGetSymbolAddress(&pv, g_hmoe);    float* p_hmoe    = (float*)pv;
    cudaGetSymbolAddress(&pv, g_actmoe);  float* p_actmoe  = (float*)pv;
    cudaGetSymbolAddress(&pv, g_hsh);     float* p_hsh     = (float*)pv;
    cudaGetSymbolAddress(&pv, g_actsh);   float* p_actsh   = (float*)pv;
    cudaGetSymbolAddress(&pv, g_outflat); float* p_outflat = (float*)pv;
    cudaGetSymbolAddress(&pv, g_scale1);  float* p_scale1  = (float*)pv;
    cudaGetSymbolAddress(&pv, g_scale2);  float* p_scale2  = (float*)pv;
    cudaGetSymbolAddress(&pv, g_tg1);     float* p_tg1     = (float*)pv;
    cudaGetSymbolAddress(&pv, g_rowmap);  int*   p_rowmap  = (int*)pv;
    cudaGetSymbolAddress(&pv, g_rscale);  float* p_rscale  = (float*)pv;

    const float* NFP = nullptr;
    const int*   NIP = nullptr;

    // 1. modulation
    mod_kernel<<<1536, 256>>>(temb, W_mod, b_mod);
    // 2. context projection: [1024,1536] = enc[1024,3584] @ W_enc^T + b_enc
    gemm_nt<1><<<dim3(12, 8, 1), 256>>>(enc, W_enc, p_ctx, BSZ*TXT, DIMM, JD,
                                        0, 0, 0, b_enc, NFP, NFP, NIP, NFP);
    // 3. LN1 * scale1
    ln_mod_kernel<<<NTOK, 256>>>(hidden, p_scale1, p_imgmod, nullptr);
    // 4. projections
    gemm_nt<0><<<dim3(12, 16, 1), 256>>>(p_imgmod, Wq, p_q, NTOK, DIMM, DIMM,
                                         0, 0, 0, NFP, NFP, NFP, NIP, NFP);
    gemm_nt<0><<<dim3(4, 16, 1), 256>>>(p_imgmod, Wk, p_kimg, NTOK, IKV, DIMM,
                                        0, 0, 0, NFP, NFP, NFP, NIP, NFP);
    gemm_nt<0><<<dim3(4, 16, 1), 256>>>(p_imgmod, Wv, p_vimg, NTOK, IKV, DIMM,
                                        0, 0, 0, NFP, NFP, NFP, NIP, NFP);
    gemm_nt<0><<<dim3(4, 8, 1), 256>>>(p_ctx, Wak, p_ktxt, BSZ*TXT, IKV, DIMM,
                                       0, 0, 0, NFP, NFP, NFP, NIP, NFP);
    gemm_nt<0><<<dim3(4, 8, 1), 256>>>(p_ctx, Wav, p_vtxt, BSZ*TXT, IKV, DIMM,
                                       0, 0, 0, NFP, NFP, NFP, NIP, NFP);
    // 5. norms + repack
    rms_q_kernel<<<3072, 256>>>(nq_w);
    kv_repack_kernel<<<1536, 256>>>(nk_w, nak_w);
    // 6. attention
    flash_kernel<<<dim3(SEQ/32, NH, BSZ), 256>>>();
    // 7. output proj + gated residual
    gemm_nt<2><<<dim3(12, 16, 1), 256>>>(p_attn, Wo, p_hs1, NTOK, DIMM, DIMM,
                                         0, 0, 0, NFP, hidden, p_tg1, NIP, NFP);
    // 8. LN2
    ln_mod_kernel<<<NTOK, 256>>>(p_hs1, p_scale2, p_mod2, p_normed2);
    // 9. router
    tembdot_kernel<<<1, 1024>>>(temb, Wg);
    router_kernel<<<NTOK, 128>>>(Wg);
    topk_kernel<<<BSZ*NE, 512>>>();
    zero_sums_kernel<<<8, 256>>>();
    sum_acc_kernel<<<64, 256>>>();
    gate_norm_kernel<<<64, 256>>>();
    gather_kernel<<<MROWS, 256>>>();
    // 10. expert GEMM 1 (batched over 16 experts)
    gemm_nt<0><<<dim3(21, 8, 16), 256>>>(p_routed, We_in, p_hmoe,
                                         BSZ*CAP, 2*NI, DIMM,
                                         (long long)BSZ*CAP*DIMM,
                                         (long long)2*NI*DIMM,
                                         (long long)BSZ*CAP*2*NI,
                                         NFP, NFP, NFP, NIP, NFP);
    swiglu_kernel<<<MROWS, 256>>>(p_hmoe, p_actmoe);
    // 11. shared expert
    gemm_nt<0><<<dim3(21, 16, 1), 256>>>(p_mod2, Ws_in, p_hsh, NTOK, 2*NI, DIMM,
                                         0, 0, 0, NFP, NFP, NFP, NIP, NFP);
    swiglu_kernel<<<NTOK, 256>>>(p_hsh, p_actsh);
    gemm_nt<0><<<dim3(12, 16, 1), 256>>>(p_actsh, Ws_out, p_outflat, NTOK, DIMM, NI,
                                         0, 0, 0, NFP, NFP, NFP, NIP, NFP);
    // 12. expert GEMM 2 with atomic scatter onto shared output
    gemm_nt<3><<<dim3(12, 8, 16), 256>>>(p_actmoe, We_out, p_outflat,
                                         BSZ*CAP, DIMM, NI,
                                         (long long)BSZ*CAP*NI,
                                         (long long)DIMM*NI,
                                         0, NFP, NFP, NFP, p_rowmap, p_rscale);
    // 13. final gated residual
    final_kernel<<<NTOK, 256>>>(out);
}

// round 4
// speedup vs baseline: 1.0010x; 1.0010x over previous
#include <cuda_runtime.h>
#include <math.h>

#define BSZ 2
#define SEQ 1024
#define TXT 512
#define DIMM 1536
#define NH 12
#define HDD 128
#define NKV 4
#define JD 3584
#define NE 16
#define NI 1344
#define CAP 512
#define LTOT 1536      // SEQ + TXT
#define NTOK 2048      // BSZ*SEQ
#define MROWS 16384    // NE*BSZ*CAP
#define IKV 512        // NKV*HDD
#define REP 3          // NH/NKV
#define EPSL 1e-6f

// ------------------------- scratch (device globals) -------------------------
__device__ float g_scale1[BSZ*DIMM];
__device__ float g_tg1[BSZ*DIMM];
__device__ float g_scale2[BSZ*DIMM];
__device__ float g_tg2[BSZ*DIMM];
__device__ float g_ctx[BSZ*TXT*DIMM];
__device__ float g_imgmod[NTOK*DIMM];
__device__ float g_q[NTOK*DIMM];
__device__ float g_kimg[NTOK*IKV];
__device__ float g_vimg[NTOK*IKV];
__device__ float g_ktxt[BSZ*TXT*IKV];
__device__ float g_vtxt[BSZ*TXT*IKV];
__device__ float g_k[BSZ*NKV*LTOT*HDD];
__device__ float g_v[BSZ*NKV*LTOT*HDD];
__device__ float g_attn[NTOK*DIMM];
__device__ float g_hs1[NTOK*DIMM];
__device__ float g_normed2[NTOK*DIMM];
__device__ float g_mod2[NTOK*DIMM];
__device__ float g_tembdot[BSZ*NE];
__device__ float g_aff[BSZ*NE*SEQ];
__device__ int   g_topidx[BSZ*NE*CAP];
__device__ float g_gating[BSZ*NE*CAP];
__device__ float g_sums[NTOK];
__device__ int   g_rowmap[MROWS];
__device__ float g_rscale[MROWS];
__device__ float g_routed[MROWS*DIMM];
__device__ float g_hmoe[MROWS*2*NI];
__device__ float g_actmoe[MROWS*NI];
__device__ float g_hsh[NTOK*2*NI];
__device__ float g_actsh[NTOK*NI];
__device__ float g_outflat[NTOK*DIMM];

// ------------------------- modulation: mod = silu(temb) @ W_mod^T + b -------
__global__ __launch_bounds__(256) void mod_kernel(const float* __restrict__ temb,
                                                  const float* __restrict__ Wm,
                                                  const float* __restrict__ bm) {
    int gw = (blockIdx.x * blockDim.x + threadIdx.x) >> 5;
    int lane = threadIdx.x & 31;
    if (gw >= BSZ * 4 * DIMM) return;
    int b = gw / (4 * DIMM);
    int j = gw - b * 4 * DIMM;
    const float* t = temb + b * DIMM;
    const float* w = Wm + (size_t)j * DIMM;
    float acc = 0.f;
    for (int kk = lane; kk < DIMM; kk += 32) {
        float x = t[kk];
        acc += (x / (1.f + __expf(-x))) * w[kk];
    }
    #pragma unroll
    for (int o = 16; o; o >>= 1) acc += __shfl_xor_sync(0xffffffffu, acc, o);
    if (lane == 0) {
        acc += bm[j];
        int q = j / DIMM, c = j - q * DIMM;
        if (q == 0)      g_scale1[b*DIMM + c] = 1.f + acc;
        else if (q == 1) g_tg1[b*DIMM + c]    = tanhf(fminf(fmaxf(acc, -2.f), 2.f));
        else if (q == 2) g_scale2[b*DIMM + c] = 1.f + acc;
        else             g_tg2[b*DIMM + c]    = tanhf(fminf(fmaxf(acc, -2.f), 2.f));
    }
}

// ------------------------- generic NT SGEMM ---------------------------------
// C[M,N] = A[M,K] * B[N,K]^T.  M,N multiples of 128; K multiple of 16.
// EPI 0: store   1: +bias[n]   2: C = resid + gate[b][n]*acc   3: atomic scatter
template<int EPI>
__global__ __launch_bounds__(256) void gemm_nt(
    const float* __restrict__ A, const float* __restrict__ B, float* __restrict__ C,
    int M, int N, int K,
    long long sA, long long sB, long long sC,
    const float* __restrict__ bias,
    const float* __restrict__ resid, const float* __restrict__ gate,
    const int* __restrict__ rowmap, const float* __restrict__ rscale)
{
    __shared__ float As[16][132];
    __shared__ float Bs[16][132];
    const int z = blockIdx.z;
    A += (long long)z * sA;
    B += (long long)z * sB;
    const int tid = threadIdx.x;
    const int m0 = blockIdx.y * 128, n0 = blockIdx.x * 128;
    const int ty = tid >> 4, tx = tid & 15;
    const int row = ty * 8, col = tx * 8;
    float acc[8][8];
    #pragma unroll
    for (int i = 0; i < 8; i++)
        #pragma unroll
        for (int j = 0; j < 8; j++) acc[i][j] = 0.f;

    for (int k0 = 0; k0 < K; k0 += 16) {
        #pragma unroll
        for (int i = 0; i < 2; i++) {
            int id = (tid << 1) + i;
            int r = id >> 2, c = (id & 3) << 2;
            float4 va = *(const float4*)(A + (long long)(m0 + r) * K + (k0 + c));
            As[c][r] = va.x; As[c+1][r] = va.y; As[c+2][r] = va.z; As[c+3][r] = va.w;
            float4 vb = *(const float4*)(B + (long long)(n0 + r) * K + (k0 + c));
            Bs[c][r] = vb.x; Bs[c+1][r] = vb.y; Bs[c+2][r] = vb.z; Bs[c+3][r] = vb.w;
        }
        __syncthreads();
        #pragma unroll
        for (int kk = 0; kk < 16; kk++) {
            float a[8], bb[8];
            *(float4*)(a)    = *(const float4*)&As[kk][row];
            *(float4*)(a+4)  = *(const float4*)&As[kk][row+4];
            *(float4*)(bb)   = *(const float4*)&Bs[kk][col];
            *(float4*)(bb+4) = *(const float4*)&Bs[kk][col+4];
            #pragma unroll
            for (int i = 0; i < 8; i++)
                #pragma unroll
                for (int j = 0; j < 8; j++) acc[i][j] += a[i] * bb[j];
        }
        __syncthreads();
    }

    if (EPI == 3) {
        #pragma unroll
        for (int i = 0; i < 8; i++) {
            int gr = z * M + m0 + row + i;
            int trow = rowmap[gr];
            float s = rscale[gr];
            float* cp = C + (long long)trow * N + n0 + col;
            #pragma unroll
            for (int j = 0; j < 8; j++) atomicAdd(&cp[j], acc[i][j] * s);
        }
    } else {
        float* Cz = C + (long long)z * sC;
        #pragma unroll
        for (int i = 0; i < 8; i++) {
            int m = m0 + row + i;
            long long off = (long long)m * N + n0 + col;
            float v[8];
            #pragma unroll
            for (int j = 0; j < 8; j++) {
                float x = acc[i][j];
                if (EPI == 1) x += bias[n0 + col + j];
                if (EPI == 2) x = resid[off + j] + gate[(m / SEQ) * N + n0 + col + j] * x;
                v[j] = x;
            }
            *(float4*)(Cz + off)     = *(float4*)(v);
            *(float4*)(Cz + off + 4) = *(float4*)(v + 4);
        }
    }
}

// ------------------------- LayerNorm (+ scale, optional normed out) ---------
__global__ __launch_bounds__(256) void ln_mod_kernel(const float* __restrict__ in,
                                                     const float* __restrict__ scale,
                                                     float* __restrict__ outmod,
                                                     float* __restrict__ outnorm) {
    int rowi = blockIdx.x;
    int b = rowi >> 10;
    const float* x = in + (size_t)rowi * DIMM;
    float s = 0.f, sq = 0.f;
    for (int d = threadIdx.x; d < DIMM; d += 256) { float v = x[d]; s += v; sq += v * v; }
    #pragma unroll
    for (int o = 16; o; o >>= 1) {
        s  += __shfl_xor_sync(0xffffffffu, s,  o);
        sq += __shfl_xor_sync(0xffffffffu, sq, o);
    }
    __shared__ float rs[8], rq[8], mv[2];
    int w = threadIdx.x >> 5;
    if ((threadIdx.x & 31) == 0) { rs[w] = s; rq[w] = sq; }
    __syncthreads();
    if (threadIdx.x == 0) {
        float S = 0.f, Q = 0.f;
        for (int i = 0; i < 8; i++) { S += rs[i]; Q += rq[i]; }
        float mean = S / DIMM;
        float var = Q / DIMM - mean * mean;
        mv[0] = mean; mv[1] = rsqrtf(var + EPSL);
    }
    __syncthreads();
    float mean = mv[0], rstd = mv[1];
    const float* sc = scale + (size_t)b * DIMM;
    for (int d = threadIdx.x; d < DIMM; d += 256) {
        float n = (x[d] - mean) * rstd;
        if (outnorm) outnorm[(size_t)rowi * DIMM + d] = n;
        outmod[(size_t)rowi * DIMM + d] = n * sc[d];
    }
}

// ------------------------- per-head RMSNorm of Q ----------------------------
__global__ __launch_bounds__(256) void rms_q_kernel(const float* __restrict__ w) {
    int gw = (blockIdx.x * blockDim.x + threadIdx.x) >> 5;
    if (gw >= NTOK * NH) return;
    int lane = threadIdx.x & 31;
    float* p = g_q + (size_t)gw * HDD;
    int d4 = lane << 2;
    float4 v = *(float4*)(p + d4);
    float ss = v.x*v.x + v.y*v.y + v.z*v.z + v.w*v.w;
    #pragma unroll
    for (int o = 16; o; o >>= 1) ss += __shfl_xor_sync(0xffffffffu, ss, o);
    float r = rsqrtf(ss / HDD + EPSL);
    float4 wv = *(const float4*)(w + d4);
    v.x *= r * wv.x; v.y *= r * wv.y; v.z *= r * wv.z; v.w *= r * wv.w;
    *(float4*)(p + d4) = v;
}

// ------------------------- K RMS + K/V repack to [b][kv][L][hd] -------------
__global__ __launch_bounds__(256) void kv_repack_kernel(const float* __restrict__ nk,
                                                        const float* __restrict__ nak) {
    int gw = (blockIdx.x * blockDim.x + threadIdx.x) >> 5;
    if (gw >= BSZ * NKV * LTOT) return;
    int lane = threadIdx.x & 31;
    int l = gw % LTOT;
    int bk = gw / LTOT;
    int kv = bk % NKV, b = bk / NKV;
    const float *ksrc, *vsrc, *w;
    if (l < SEQ) {
        ksrc = g_kimg + (size_t)(b * SEQ + l) * IKV + kv * HDD;
        vsrc = g_vimg + (size_t)(b * SEQ + l) * IKV + kv * HDD;
        w = nk;
    } else {
        int tt = l - SEQ;
        ksrc = g_ktxt + (size_t)(b * TXT + tt) * IKV + kv * HDD;
        vsrc = g_vtxt + (size_t)(b * TXT + tt) * IKV + kv * HDD;
        w = nak;
    }
    int d4 = lane << 2;
    float4 kvv = *(const float4*)(ksrc + d4);
    float ss = kvv.x*kvv.x + kvv.y*kvv.y + kvv.z*kvv.z + kvv.w*kvv.w;
    #pragma unroll
    for (int o = 16; o; o >>= 1) ss += __shfl_xor_sync(0xffffffffu, ss, o);
    float r = rsqrtf(ss / HDD + EPSL);
    float4 wv = *(const float4*)(w + d4);
    kvv.x *= r * wv.x; kvv.y *= r * wv.y; kvv.z *= r * wv.z; kvv.w *= r * wv.w;
    size_t dst = ((size_t)(b * NKV + kv) * LTOT + l) * HDD + d4;
    *(float4*)(g_k + dst) = kvv;
    *(float4*)(g_v + dst) = *(const float4*)(vsrc + d4);
}

// ------------------------- flash attention ----------------------------------
__global__ __launch_bounds__(256) void flash_kernel() {
    __shared__ float Qs[32][129];
    __shared__ float KVs[32][129];
    __shared__ float Ss[32][33];
    const int q0 = blockIdx.x * 32;
    const int h = blockIdx.y;
    const int b = blockIdx.z;
    const int kv = h / REP;
    const int t = threadIdx.x;
    for (int idx = t; idx < 1024; idx += 256) {
        int qi = idx >> 5, d4 = (idx & 31) << 2;
        float4 v = *(const float4*)(g_q + (size_t)(b * SEQ + q0 + qi) * DIMM + h * HDD + d4);
        Qs[qi][d4] = v.x; Qs[qi][d4+1] = v.y; Qs[qi][d4+2] = v.z; Qs[qi][d4+3] = v.w;
    }
    const int q = t >> 3, dg = t & 7;
    float acc[16];
    #pragma unroll
    for (int i = 0; i < 16; i++) acc[i] = 0.f;
    float m = -1e30f, l = 0.f;
    const float sc = 0.08838834764831845f;  // 1/sqrt(128)
    const float* kbase = g_k + (size_t)(b * NKV + kv) * LTOT * HDD;
    const float* vbase = g_v + (size_t)(b * NKV + kv) * LTOT * HDD;
    __syncthreads();
    for (int k0 = 0; k0 < LTOT; k0 += 32) {
        for (int idx = t; idx < 1024; idx += 256) {
            int ki = idx >> 5, d4 = (idx & 31) << 2;
            float4 v = *(const float4*)(kbase + (size_t)(k0 + ki) * HDD + d4);
            KVs[ki][d4] = v.x; KVs[ki][d4+1] = v.y; KVs[ki][d4+2] = v.z; KVs[ki][d4+3] = v.w;
        }
        __syncthreads();
        {
            int kb = dg << 2;
            float s0 = 0.f, s1 = 0.f, s2 = 0.f, s3 = 0.f;
            #pragma unroll 4
            for (int d = 0; d < 128; d++) {
                float qv = Qs[q][d];
                s0 += qv * KVs[kb][d];
                s1 += qv * KVs[kb+1][d];
                s2 += qv * KVs[kb+2][d];
                s3 += qv * KVs[kb+3][d];
            }
            Ss[q][kb] = s0 * sc; Ss[q][kb+1] = s1 * sc;
            Ss[q][kb+2] = s2 * sc; Ss[q][kb+3] = s3 * sc;
        }
        __syncthreads();
        float srow[32];
        float rmax = -1e30f;
        #pragma unroll
        for (int k = 0; k < 32; k++) { srow[k] = Ss[q][k]; rmax = fmaxf(rmax, srow[k]); }
        // load V into KVs (K reads finished at previous sync)
        for (int idx = t; idx < 1024; idx += 256) {
            int ki = idx >> 5, d4 = (idx & 31) << 2;
            float4 v = *(const float4*)(vbase + (size_t)(k0 + ki) * HDD + d4);
            KVs[ki][d4] = v.x; KVs[ki][d4+1] = v.y; KVs[ki][d4+2] = v.z; KVs[ki][d4+3] = v.w;
        }
        float newm = fmaxf(m, rmax);
        float corr = __expf(m - newm);
        float psum = 0.f;
        #pragma unroll
        for (int k = 0; k < 32; k++) { srow[k] = __expf(srow[k] - newm); psum += srow[k]; }
        l = l * corr + psum;
        m = newm;
        #pragma unroll
        for (int i = 0; i < 16; i++) acc[i] *= corr;
        __syncthreads();
        #pragma unroll
        for (int k = 0; k < 32; k++) {
            float p = srow[k];
            #pragma unroll
            for (int i = 0; i < 16; i++) acc[i] += p * KVs[k][dg + (i << 3)];
        }
        __syncthreads();
    }
    float inv = 1.f / l;
    float* op = g_attn + (size_t)(b * SEQ + q0 + q) * DIMM + h * HDD;
    #pragma unroll
    for (int i = 0; i < 16; i++) op[dg + (i << 3)] = acc[i] * inv;
}

// ------------------------- router ------------------------------------------
__global__ __launch_bounds__(1024) void tembdot_kernel(const float* __restrict__ temb,
                                                       const float* __restrict__ Wg) {
    int wid = threadIdx.x >> 5, lane = threadIdx.x & 31;
    int b = wid / NE, e = wid % NE;
    const float* t = temb + b * DIMM;
    const float* w = Wg + (size_t)e * 2 * DIMM;
    float acc = 0.f;
    for (int d = lane; d < DIMM; d += 32) acc += t[d] * w[d];
    #pragma unroll
    for (int o = 16; o; o >>= 1) acc += __shfl_xor_sync(0xffffffffu, acc, o);
    if (lane == 0) g_tembdot[wid] = acc;
}

__global__ __launch_bounds__(128) void router_kernel(const float* __restrict__ Wg) {
    __shared__ float lg[NE];
    int tokid = blockIdx.x;
    int b = tokid >> 10, s = tokid & 1023;
    int w = threadIdx.x >> 5, lane = threadIdx.x & 31;
    const float* x = g_normed2 + (size_t)tokid * DIMM;
    for (int e = w * 4; e < w * 4 + 4; e++) {
        const float* wg = Wg + (size_t)e * 2 * DIMM + DIMM;
        float acc = 0.f;
        for (int d = lane; d < DIMM; d += 32) acc += x[d] * wg[d];
        #pragma unroll
        for (int o = 16; o; o >>= 1) acc += __shfl_xor_sync(0xffffffffu, acc, o);
        if (lane == 0) lg[e] = acc + g_tembdot[b * NE + e];
    }
    __syncthreads();
    if (threadIdx.x == 0) {
        float mx = -1e30f;
        for (int e = 0; e < NE; e++) mx = fmaxf(mx, lg[e]);
        float ex[NE], sm = 0.f;
        for (int e = 0; e < NE; e++) { ex[e] = __expf(lg[e] - mx); sm += ex[e]; }
        float inv = 1.f / sm;
        for (int e = 0; e < NE; e++)
            g_aff[((size_t)(b * NE + e)) * SEQ + s] = ex[e] * inv;
    }
}

// ------------------------- exact top-k via bitonic sort ---------------------
__global__ __launch_bounds__(512) void topk_kernel() {
    __shared__ float v[1024];
    __shared__ int   id[1024];
    int be = blockIdx.x;
    const float* rowp = g_aff + (size_t)be * SEQ;
    int t = threadIdx.x;
    for (int i = t; i < 1024; i += 512) { v[i] = rowp[i]; id[i] = i; }
    __syncthreads();
    for (int k = 2; k <= 1024; k <<= 1) {
        for (int j = k >> 1; j > 0; j >>= 1) {
            for (int i = t; i < 1024; i += 512) {
                int ixj = i ^ j;
                if (ixj > i) {
                    bool up = ((i & k) == 0);
                    float va = v[i], vb = v[ixj];
                    int ia = id[i], ib = id[ixj];
                    bool a_first = (va > vb) || (va == vb && ia < ib);
                    bool sw = up ? !a_first : a_first;
                    if (sw) { v[i] = vb; v[ixj] = va; id[i] = ib; id[ixj] = ia; }
                }
            }
            __syncthreads();
        }
    }
    if (t < CAP) {
        g_gating[be * CAP + t] = v[t];
        g_topidx[be * CAP + t] = id[t];
    }
}

__global__ void zero_sums_kernel() {
    int i = blockIdx.x * blockDim.x + threadIdx.x;
    if (i < NTOK) g_sums[i] = 0.f;
}

__global__ void sum_acc_kernel() {
    int i = blockIdx.x * blockDim.x + threadIdx.x;
    if (i >= BSZ * NE * CAP) return;
    int be = i / CAP;
    int b = be / NE;
    int tok = b * SEQ + g_topidx[i];
    atomicAdd(&g_sums[tok], g_gating[i]);
}

__global__ void gate_norm_kernel() {
    int i = blockIdx.x * blockDim.x + threadIdx.x;
    if (i >= BSZ * NE * CAP) return;
    int c = i % CAP;
    int be = i / CAP;
    int b = be / NE, e = be % NE;
    int tok = b * SEQ + g_topidx[i];
    float g = g_gating[i] / (g_sums[tok] + 1e-12f) * 2.5f;
    int rowflat = (e * BSZ + b) * CAP + c;
    g_rowmap[rowflat] = tok;
    g_rscale[rowflat] = g;
}

__global__ __launch_bounds__(256) void gather_kernel() {
    int r = blockIdx.x;
    int src = g_rowmap[r];
    const float4* s = (const float4*)(g_mod2 + (size_t)src * DIMM);
    float4* d = (float4*)(g_routed + (size_t)r * DIMM);
    for (int i = threadIdx.x; i < DIMM / 4; i += 256) d[i] = s[i];
}

// ------------------------- swiglu activation --------------------------------
__global__ __launch_bounds__(256) void swiglu_kernel(const float* __restrict__ h,
                                                     float* __restrict__ out) {
    int r = blockIdx.x;
    const float4* a = (const float4*)(h + (size_t)r * 2 * NI);
    const float4* g = (const float4*)(h + (size_t)r * 2 * NI + NI);
    float4* o = (float4*)(out + (size_t)r * NI);
    for (int i = threadIdx.x; i < NI / 4; i += 256) {
        float4 av = a[i], gv = g[i], ov;
        ov.x = av.x * (gv.x / (1.f + __expf(-gv.x)));
        ov.y = av.y * (gv.y / (1.f + __expf(-gv.y)));
        ov.z = av.z * (gv.z / (1.f + __expf(-gv.z)));
        ov.w = av.w * (gv.w / (1.f + __expf(-gv.w)));
        o[i] = ov;
    }
}

// ------------------------- final residual -----------------------------------
__global__ __launch_bounds__(256) void final_kernel(float* __restrict__ out) {
    int r = blockIdx.x;
    int b = r >> 10;
    const float4* hs = (const float4*)(g_hs1 + (size_t)r * DIMM);
    const float4* mo = (const float4*)(g_outflat + (size_t)r * DIMM);
    const float4* gg = (const float4*)(g_tg2 + (size_t)b * DIMM);
    float4* o = (float4*)(out + (size_t)r * DIMM);
    for (int i = threadIdx.x; i < DIMM / 4; i += 256) {
        float4 h = hs[i], m = mo[i], g = gg[i], v;
        v.x = h.x + g.x * m.x; v.y = h.y + g.y * m.y;
        v.z = h.z + g.z * m.z; v.w = h.w + g.w * m.w;
        o[i] = v;
    }
}

// ------------------------- launcher -----------------------------------------
extern "C" void kernel_launch(void* const* d_in, const int* in_sizes, int n_in,
                              void* d_out, int out_size) {
    const float* hidden = (const float*)d_in[0];
    const float* enc    = (const float*)d_in[1];
    const float* temb   = (const float*)d_in[2];
    const float* W_mod  = (const float*)d_in[3];
    const float* b_mod  = (const float*)d_in[4];
    const float* W_enc  = (const float*)d_in[5];
    const float* b_enc  = (const float*)d_in[6];
    const float* Wq     = (const float*)d_in[7];
    const float* Wk     = (const float*)d_in[8];
    const float* Wv     = (const float*)d_in[9];
    const float* Wak    = (const float*)d_in[10];
    const float* Wav    = (const float*)d_in[11];
    const float* nq_w   = (const float*)d_in[12];
    const float* nk_w   = (const float*)d_in[13];
    const float* nak_w  = (const float*)d_in[14];
    const float* Wo     = (const float*)d_in[15];
    const float* Wg     = (const float*)d_in[16];
    const float* We_in  = (const float*)d_in[17];
    const float* We_out = (const float*)d_in[18];
    const float* Ws_in  = (const float*)d_in[19];
    const float* Ws_out = (const float*)d_in[20];
    float* out = (float*)d_out;

    void* pv;
    cudaGetSymbolAddress(&pv, g_ctx);     float* p_ctx     = (float*)pv;
    cudaGetSymbolAddress(&pv, g_imgmod);  float* p_imgmod  = (float*)pv;
    cudaGetSymbolAddress(&pv, g_q);       float* p_q       = (float*)pv;
    cudaGetSymbolAddress(&pv, g_kimg);    float* p_kimg    = (float*)pv;
    cudaGetSymbolAddress(&pv, g_vimg);    float* p_vimg    = (float*)pv;
    cudaGetSymbolAddress(&pv, g_ktxt);    float* p_ktxt    = (float*)pv;
    cudaGetSymbolAddress(&pv, g_vtxt);    float* p_vtxt    = (float*)pv;
    cudaGetSymbolAddress(&pv, g_attn);    float* p_attn    = (float*)pv;
    cudaGetSymbolAddress(&pv, g_hs1);     float* p_hs1     = (float*)pv;
    cudaGetSymbolAddress(&pv, g_normed2); float* p_normed2 = (float*)pv;
    cudaGetSymbolAddress(&pv, g_mod2);    float* p_mod2    = (float*)pv;
    cudaGetSymbolAddress(&pv, g_routed);  float* p_routed  = (float*)pv;
    cudaGetSymbolAddress(&pv, g_hmoe);    float* p_hmoe    = (float*)pv;
    cudaGetSymbolAddress(&pv, g_actmoe);  float* p_actmoe  = (float*)pv;
    cudaGetSymbolAddress(&pv, g_hsh);     float* p_hsh     = (float*)pv;
    cudaGetSymbolAddress(&pv, g_actsh);   float* p_actsh   = (float*)pv;
    cudaGetSymbolAddress(&pv, g_outflat); float* p_outflat = (float*)pv;
    cudaGetSymbolAddress(&pv, g_scale1);  float* p_scale1  = (float*)pv;
    cudaGetSymbolAddress(&pv, g_scale2);  float* p_scale2  = (float*)pv;
    cudaGetSymbolAddress(&pv, g_tg1);     float* p_tg1     = (float*)pv;
    cudaGetSymbolAddress(&pv, g_rowmap);  int*   p_rowmap  = (int*)pv;
    cudaGetSymbolAddress(&pv, g_rscale);  float* p_rscale  = (float*)pv;

    const float* NFP = nullptr;
    const int*   NIP = nullptr;

    // 1. modulation
    mod_kernel<<<1536, 256>>>(temb, W_mod, b_mod);
    // 2. context projection: [1024,1536] = enc[1024,3584] @ W_enc^T + b_enc
    gemm_nt<1><<<dim3(12, 8, 1), 256>>>(enc, W_enc, p_ctx, BSZ*TXT, DIMM, JD,
                                        0, 0, 0, b_enc, NFP, NFP, NIP, NFP);
    // 3. LN1 * scale1
    ln_mod_kernel<<<NTOK, 256>>>(hidden, p_scale1, p_imgmod, nullptr);
    // 4. projections
    gemm_nt<0><<<dim3(12, 16, 1), 256>>>(p_imgmod, Wq, p_q, NTOK, DIMM, DIMM,
                                         0, 0, 0, NFP, NFP, NFP, NIP, NFP);
    gemm_nt<0><<<dim3(4, 16, 1), 256>>>(p_imgmod, Wk, p_kimg, NTOK, IKV, DIMM,
                                        0, 0, 0, NFP, NFP, NFP, NIP, NFP);
    gemm_nt<0><<<dim3(4, 16, 1), 256>>>(p_imgmod, Wv, p_vimg, NTOK, IKV, DIMM,
                                        0, 0, 0, NFP, NFP, NFP, NIP, NFP);
    gemm_nt<0><<<dim3(4, 8, 1), 256>>>(p_ctx, Wak, p_ktxt, BSZ*TXT, IKV, DIMM,
                                       0, 0, 0, NFP, NFP, NFP, NIP, NFP);
    gemm_nt<0><<<dim3(4, 8, 1), 256>>>(p_ctx, Wav, p_vtxt, BSZ*TXT, IKV, DIMM,
                                       0, 0, 0, NFP, NFP, NFP, NIP, NFP);
    // 5. norms + repack
    rms_q_kernel<<<3072, 256>>>(nq_w);
    kv_repack_kernel<<<1536, 256>>>(nk_w, nak_w);
    // 6. attention
    flash_kernel<<<dim3(SEQ/32, NH, BSZ), 256>>>();
    // 7. output proj + gated residual
    gemm_nt<2><<<dim3(12, 16, 1), 256>>>(p_attn, Wo, p_hs1, NTOK, DIMM, DIMM,
                                         0, 0, 0, NFP, hidden, p_tg1, NIP, NFP);
    // 8. LN2
    ln_mod_kernel<<<NTOK, 256>>>(p_hs1, p_scale2, p_mod2, p_normed2);
    // 9. router
    tembdot_kernel<<<1, 1024>>>(temb, Wg);
    router_kernel<<<NTOK, 128>>>(Wg);
    topk_kernel<<<BSZ*NE, 512>>>();
    zero_sums_kernel<<<8, 256>>>();
    sum_acc_kernel<<<64, 256>>>();
    gate_norm_kernel<<<64, 256>>>();
    gather_kernel<<<MROWS, 256>>>();
    // 10. expert GEMM 1 (batched over 16 experts)
    gemm_nt<0><<<dim3(21, 8, 16), 256>>>(p_routed, We_in, p_hmoe,
                                         BSZ*CAP, 2*NI, DIMM,
                                         (long long)BSZ*CAP*DIMM,
                                         (long long)2*NI*DIMM,
                                         (long long)BSZ*CAP*2*NI,
                                         NFP, NFP, NFP, NIP, NFP);
    swiglu_kernel<<<MROWS, 256>>>(p_hmoe, p_actmoe);
    // 11. shared expert
    gemm_nt<0><<<dim3(21, 16, 1), 256>>>(p_mod2, Ws_in, p_hsh, NTOK, 2*NI, DIMM,
                                         0, 0, 0, NFP, NFP, NFP, NIP, NFP);
    swiglu_kernel<<<NTOK, 256>>>(p_hsh, p_actsh);
    gemm_nt<0><<<dim3(12, 16, 1), 256>>>(p_actsh, Ws_out, p_outflat, NTOK, DIMM, NI,
                                         0, 0, 0, NFP, NFP, NFP, NIP, NFP);
    // 12. expert GEMM 2 with atomic scatter onto shared output
    gemm_nt<3><<<dim3(12, 8, 16), 256>>>(p_actmoe, We_out, p_outflat,
                                         BSZ*CAP, DIMM, NI,
                                         (long long)BSZ*CAP*NI,
                                         (long long)DIMM*NI,
                                         0, NFP, NFP, NFP, p_rowmap, p_rscale);
    // 13. final gated residual
    final_kernel<<<NTOK, 256>>>(out);
}

// round 6
// speedup vs baseline: 1.7346x; 1.7328x over previous
#include <cuda_runtime.h>
#include <cuda_fp16.h>
#include <math.h>
#include <stdint.h>

#define BSZ 2
#define SEQ 1024
#define TXT 512
#define DIMM 1536
#define NH 12
#define HDD 128
#define NKV 4
#define JD 3584
#define NE 16
#define NI 1344
#define CAP 512
#define LTOT 1536      // SEQ + TXT
#define NTOK 2048      // BSZ*SEQ
#define MROWS 16384    // NE*BSZ*CAP
#define IKV 512        // NKV*HDD
#define REP 3          // NH/NKV
#define EPSL 1e-6f

// ------------------------- scratch (device globals) -------------------------
__device__ float g_scale1[BSZ*DIMM];
__device__ float g_tg1[BSZ*DIMM];
__device__ float g_scale2[BSZ*DIMM];
__device__ float g_tg2[BSZ*DIMM];
__device__ float g_ctx[BSZ*TXT*DIMM];
__device__ float g_imgmod[NTOK*DIMM];
__device__ float g_q[NTOK*DIMM];
__device__ float g_kimg[NTOK*IKV];
__device__ float g_vimg[NTOK*IKV];
__device__ float g_ktxt[BSZ*TXT*IKV];
__device__ float g_vtxt[BSZ*TXT*IKV];
__device__ float g_k[BSZ*NKV*LTOT*HDD];
__device__ float g_v[BSZ*NKV*LTOT*HDD];
__device__ float g_attn[NTOK*DIMM];
__device__ float g_hs1[NTOK*DIMM];
__device__ float g_normed2[NTOK*DIMM];
__device__ float g_mod2[NTOK*DIMM];
__device__ float g_tembdot[BSZ*NE];
__device__ float g_aff[BSZ*NE*SEQ];
__device__ int   g_topidx[BSZ*NE*CAP];
__device__ float g_gating[BSZ*NE*CAP];
__device__ float g_sums[NTOK];
__device__ int   g_rowmap[MROWS];
__device__ float g_rscale[MROWS];
__device__ float g_hmoe[(size_t)MROWS*2*NI];
__device__ float g_actmoe[(size_t)MROWS*NI];
__device__ float g_hsh[NTOK*2*NI];
__device__ float g_actsh[NTOK*NI];
__device__ float g_outflat[NTOK*DIMM];

// ======================= helpers ============================================
__device__ __forceinline__ uint32_t s2u(const void* p) {
    uint32_t a;
    asm("{ .reg .u64 t; cvta.to.shared.u64 t, %1; cvt.u32.u64 %0, t; }"
        : "=r"(a) : "l"(p));
    return a;
}
__device__ __forceinline__ void ld16(const float* __restrict__ p, float* d) {
    #pragma unroll
    for (int i = 0; i < 4; i++) *(float4*)(d + 4*i) = *(const float4*)(p + 4*i);
}
// 16 fp32 -> hi/lo fp16 split, packed as 2+2 uint4
__device__ __forceinline__ void cvt16(const float* f, uint4* hs, uint4* ls) {
    union { __half h[16]; uint4 u[2]; } H, L;
    #pragma unroll
    for (int i = 0; i < 16; i++) {
        __half hh = __float2half(f[i]);
        H.h[i] = hh;
        L.h[i] = __float2half(f[i] - __half2float(hh));
    }
    hs[0] = H.u[0]; hs[1] = H.u[1];
    ls[0] = L.u[0]; ls[1] = L.u[1];
}
__device__ __forceinline__ void mma16816(float* c, const uint32_t* a, const uint32_t* b) {
    asm volatile(
        "mma.sync.aligned.m16n8k16.row.col.f32.f16.f16.f32 "
        "{%0,%1,%2,%3}, {%4,%5,%6,%7}, {%8,%9}, {%0,%1,%2,%3};"
        : "+f"(c[0]), "+f"(c[1]), "+f"(c[2]), "+f"(c[3])
        : "r"(a[0]), "r"(a[1]), "r"(a[2]), "r"(a[3]), "r"(b[0]), "r"(b[1]));
}

// ======================= split-fp16 mma.sync GEMM ===========================
// C[M,N] = A[M,K] * B[N,K]^T at ~fp32 precision via extended-K f16 split:
//   A_ext = [Ah | Ah | Al],  B_ext = [Bh | Bl | Bh]  => AhBh + AhBl + AlBh
// CTA tile 128x128, source-K chunk 32 (ext 96), 256 thr = 8 warps (2x4),
// warp tile 64x32. Register prefetch of next fp32 chunk overlaps MMA.
// EPI 0: store  1: +bias[n]  2: resid + gate[b][n]*acc  3: atomic scatter
// AG: gather A rows through agather[z*M + m].
#define RSB 208                 // smem row stride bytes (96 halves + pad)
#define ASZ (128*RSB)           // 26624
#define MMSM (2*ASZ)            // 53248

template<int EPI, bool AG>
__global__ __launch_bounds__(256) void mma_gemm(
    const float* __restrict__ A, const float* __restrict__ B, float* __restrict__ C,
    int M, int N, int K,
    long long sA, long long sB, long long sC,
    const float* __restrict__ bias,
    const float* __restrict__ resid, const float* __restrict__ gate,
    const int* __restrict__ rowmap, const float* __restrict__ rscale,
    const int* __restrict__ agather)
{
    extern __shared__ char smem[];
    const int tid = threadIdx.x;
    const int wid = tid >> 5, lane = tid & 31;
    const int z = blockIdx.z;
    const int m0 = blockIdx.y * 128, n0 = blockIdx.x * 128;
    if (!AG) A += (long long)z * sA;
    B += (long long)z * sB;

    // ---- loader assignment: thread owns row lr, 16-col half lh ----
    const int lr = tid >> 1;
    const int lh = tid & 1;
    long long arow = AG ? (long long)agather[(long long)z * M + m0 + lr]
                        : (long long)(m0 + lr);
    const float* ag = A + arow * (long long)K + lh * 16;
    const float* bg = B + (long long)(n0 + lr) * K + lh * 16;
    char* Ap = smem + lr * RSB + lh * 32;
    char* Bp = smem + ASZ + lr * RSB + lh * 32;

    // ---- warp tile / ldmatrix addresses ----
    const int wm = (wid >> 2) * 64;
    const int wn = (wid & 3) * 32;
    const uint32_t sAb = s2u(smem);
    const uint32_t sBb = sAb + ASZ;
    uint32_t a_ld[4], b_ld[4];
    #pragma unroll
    for (int mt = 0; mt < 4; mt++) {
        int r = wm + mt * 16 + (lane & 15);
        a_ld[mt] = sAb + r * RSB + (lane >> 4) * 16;
    }
    #pragma unroll
    for (int nt = 0; nt < 4; nt++) {
        int r = wn + nt * 8 + (lane & 7);
        b_ld[nt] = sBb + r * RSB + ((lane >> 3) & 1) * 16;
    }

    float acc[4][4][4];
    #pragma unroll
    for (int mt = 0; mt < 4; mt++)
        #pragma unroll
        for (int nt = 0; nt < 4; nt++)
            #pragma unroll
            for (int i = 0; i < 4; i++) acc[mt][nt][i] = 0.f;

    const int NC = K >> 5;
    float pfa[16], pfb[16];
    ld16(ag, pfa);
    ld16(bg, pfb);

    for (int c = 0; c < NC; c++) {
        if (c) __syncthreads();
        // convert + store ext-K layout
        {
            uint4 h[2], l[2];
            cvt16(pfa, h, l);
            *(uint4*)(Ap +   0) = h[0]; *(uint4*)(Ap +  16) = h[1];
            *(uint4*)(Ap +  64) = h[0]; *(uint4*)(Ap +  80) = h[1];
            *(uint4*)(Ap + 128) = l[0]; *(uint4*)(Ap + 144) = l[1];
            cvt16(pfb, h, l);
            *(uint4*)(Bp +   0) = h[0]; *(uint4*)(Bp +  16) = h[1];
            *(uint4*)(Bp +  64) = l[0]; *(uint4*)(Bp +  80) = l[1];
            *(uint4*)(Bp + 128) = h[0]; *(uint4*)(Bp + 144) = h[1];
        }
        __syncthreads();
        if (c + 1 < NC) {
            ld16(ag + (c + 1) * 32, pfa);
            ld16(bg + (c + 1) * 32, pfb);
        }
        // 6 k16 steps over ext-K = 96
        #pragma unroll
        for (int ks = 0; ks < 6; ks++) {
            uint32_t af[4][4];
            #pragma unroll
            for (int mt = 0; mt < 4; mt++)
                asm volatile("ldmatrix.sync.aligned.m8n8.x4.shared.b16 {%0,%1,%2,%3}, [%4];"
                    : "=r"(af[mt][0]), "=r"(af[mt][1]), "=r"(af[mt][2]), "=r"(af[mt][3])
                    : "r"(a_ld[mt] + ks * 32));
            uint32_t bf[4][2];
            #pragma unroll
            for (int nt = 0; nt < 4; nt++)
                asm volatile("ldmatrix.sync.aligned.m8n8.x2.shared.b16 {%0,%1}, [%2];"
                    : "=r"(bf[nt][0]), "=r"(bf[nt][1])
                    : "r"(b_ld[nt] + ks * 32));
            #pragma unroll
            for (int mt = 0; mt < 4; mt++)
                #pragma unroll
                for (int nt = 0; nt < 4; nt++)
                    mma16816(acc[mt][nt], af[mt], bf[nt]);
        }
    }

    // ---- epilogue ----
    const int g = lane >> 2;
    const int cp2 = (lane & 3) * 2;
    #pragma unroll
    for (int mt = 0; mt < 4; mt++) {
        #pragma unroll
        for (int hh = 0; hh < 2; hh++) {
            int row = m0 + wm + mt * 16 + g + hh * 8;
            if (EPI == 3) {
                long long gr = (long long)z * M + row;
                int trow = rowmap[gr];
                float s = rscale[gr];
                float* cp = C + (long long)trow * N;
                #pragma unroll
                for (int nt = 0; nt < 4; nt++) {
                    int col = n0 + wn + nt * 8 + cp2;
                    atomicAdd(cp + col,     acc[mt][nt][hh*2]   * s);
                    atomicAdd(cp + col + 1, acc[mt][nt][hh*2+1] * s);
                }
            } else {
                float* Cz = C + (long long)z * sC + (long long)row * N;
                #pragma unroll
                for (int nt = 0; nt < 4; nt++) {
                    int col = n0 + wn + nt * 8 + cp2;
                    float v0 = acc[mt][nt][hh*2], v1 = acc[mt][nt][hh*2+1];
                    if (EPI == 1) { v0 += bias[col]; v1 += bias[col + 1]; }
                    if (EPI == 2) {
                        const float* gp = gate + (row / SEQ) * N + col;
                        const float* rp = resid + (long long)row * N + col;
                        v0 = rp[0] + gp[0] * v0;
                        v1 = rp[1] + gp[1] * v1;
                    }
                    *(float2*)(Cz + col) = make_float2(v0, v1);
                }
            }
        }
    }
}

// ------------------------- modulation: mod = silu(temb) @ W_mod^T + b -------
__global__ __launch_bounds__(256) void mod_kernel(const float* __restrict__ temb,
                                                  const float* __restrict__ Wm,
                                                  const float* __restrict__ bm) {
    int gw = (blockIdx.x * blockDim.x + threadIdx.x) >> 5;
    int lane = threadIdx.x & 31;
    if (gw >= BSZ * 4 * DIMM) return;
    int b = gw / (4 * DIMM);
    int j = gw - b * 4 * DIMM;
    const float* t = temb + b * DIMM;
    const float* w = Wm + (size_t)j * DIMM;
    float acc = 0.f;
    for (int kk = lane; kk < DIMM; kk += 32) {
        float x = t[kk];
        acc += (x / (1.f + __expf(-x))) * w[kk];
    }
    #pragma unroll
    for (int o = 16; o; o >>= 1) acc += __shfl_xor_sync(0xffffffffu, acc, o);
    if (lane == 0) {
        acc += bm[j];
        int q = j / DIMM, c = j - q * DIMM;
        if (q == 0)      g_scale1[b*DIMM + c] = 1.f + acc;
        else if (q == 1) g_tg1[b*DIMM + c]    = tanhf(fminf(fmaxf(acc, -2.f), 2.f));
        else if (q == 2) g_scale2[b*DIMM + c] = 1.f + acc;
        else             g_tg2[b*DIMM + c]    = tanhf(fminf(fmaxf(acc, -2.f), 2.f));
    }
}

// ------------------------- LayerNorm (+ scale, optional normed out) ---------
__global__ __launch_bounds__(256) void ln_mod_kernel(const float* __restrict__ in,
                                                     const float* __restrict__ scale,
                                                     float* __restrict__ outmod,
                                                     float* __restrict__ outnorm) {
    int rowi = blockIdx.x;
    int b = rowi >> 10;
    const float* x = in + (size_t)rowi * DIMM;
    float s = 0.f, sq = 0.f;
    for (int d = threadIdx.x; d < DIMM; d += 256) { float v = x[d]; s += v; sq += v * v; }
    #pragma unroll
    for (int o = 16; o; o >>= 1) {
        s  += __shfl_xor_sync(0xffffffffu, s,  o);
        sq += __shfl_xor_sync(0xffffffffu, sq, o);
    }
    __shared__ float rs[8], rq[8], mv[2];
    int w = threadIdx.x >> 5;
    if ((threadIdx.x & 31) == 0) { rs[w] = s; rq[w] = sq; }
    __syncthreads();
    if (threadIdx.x == 0) {
        float S = 0.f, Q = 0.f;
        for (int i = 0; i < 8; i++) { S += rs[i]; Q += rq[i]; }
        float mean = S / DIMM;
        float var = Q / DIMM - mean * mean;
        mv[0] = mean; mv[1] = rsqrtf(var + EPSL);
    }
    __syncthreads();
    float mean = mv[0], rstd = mv[1];
    const float* sc = scale + (size_t)b * DIMM;
    for (int d = threadIdx.x; d < DIMM; d += 256) {
        float n = (x[d] - mean) * rstd;
        if (outnorm) outnorm[(size_t)rowi * DIMM + d] = n;
        outmod[(size_t)rowi * DIMM + d] = n * sc[d];
    }
}

// ------------------------- per-head RMSNorm of Q ----------------------------
__global__ __launch_bounds__(256) void rms_q_kernel(const float* __restrict__ w) {
    int gw = (blockIdx.x * blockDim.x + threadIdx.x) >> 5;
    if (gw >= NTOK * NH) return;
    int lane = threadIdx.x & 31;
    float* p = g_q + (size_t)gw * HDD;
    int d4 = lane << 2;
    float4 v = *(float4*)(p + d4);
    float ss = v.x*v.x + v.y*v.y + v.z*v.z + v.w*v.w;
    #pragma unroll
    for (int o = 16; o; o >>= 1) ss += __shfl_xor_sync(0xffffffffu, ss, o);
    float r = rsqrtf(ss / HDD + EPSL);
    float4 wv = *(const float4*)(w + d4);
    v.x *= r * wv.x; v.y *= r * wv.y; v.z *= r * wv.z; v.w *= r * wv.w;
    *(float4*)(p + d4) = v;
}

// ------------------------- K RMS + K/V repack to [b][kv][L][hd] -------------
__global__ __launch_bounds__(256) void kv_repack_kernel(const float* __restrict__ nk,
                                                        const float* __restrict__ nak) {
    int gw = (blockIdx.x * blockDim.x + threadIdx.x) >> 5;
    if (gw >= BSZ * NKV * LTOT) return;
    int lane = threadIdx.x & 31;
    int l = gw % LTOT;
    int bk = gw / LTOT;
    int kv = bk % NKV, b = bk / NKV;
    const float *ksrc, *vsrc, *w;
    if (l < SEQ) {
        ksrc = g_kimg + (size_t)(b * SEQ + l) * IKV + kv * HDD;
        vsrc = g_vimg + (size_t)(b * SEQ + l) * IKV + kv * HDD;
        w = nk;
    } else {
        int tt = l - SEQ;
        ksrc = g_ktxt + (size_t)(b * TXT + tt) * IKV + kv * HDD;
        vsrc = g_vtxt + (size_t)(b * TXT + tt) * IKV + kv * HDD;
        w = nak;
    }
    int d4 = lane << 2;
    float4 kvv = *(const float4*)(ksrc + d4);
    float ss = kvv.x*kvv.x + kvv.y*kvv.y + kvv.z*kvv.z + kvv.w*kvv.w;
    #pragma unroll
    for (int o = 16; o; o >>= 1) ss += __shfl_xor_sync(0xffffffffu, ss, o);
    float r = rsqrtf(ss / HDD + EPSL);
    float4 wv = *(const float4*)(w + d4);
    kvv.x *= r * wv.x; kvv.y *= r * wv.y; kvv.z *= r * wv.z; kvv.w *= r * wv.w;
    size_t dst = ((size_t)(b * NKV + kv) * LTOT + l) * HDD + d4;
    *(float4*)(g_k + dst) = kvv;
    *(float4*)(g_v + dst) = *(const float4*)(vsrc + d4);
}

// ------------------------- flash attention ----------------------------------
__global__ __launch_bounds__(256) void flash_kernel() {
    __shared__ float Qs[32][129];
    __shared__ float KVs[32][129];
    __shared__ float Ss[32][33];
    const int q0 = blockIdx.x * 32;
    const int h = blockIdx.y;
    const int b = blockIdx.z;
    const int kv = h / REP;
    const int t = threadIdx.x;
    for (int idx = t; idx < 1024; idx += 256) {
        int qi = idx >> 5, d4 = (idx & 31) << 2;
        float4 v = *(const float4*)(g_q + (size_t)(b * SEQ + q0 + qi) * DIMM + h * HDD + d4);
        Qs[qi][d4] = v.x; Qs[qi][d4+1] = v.y; Qs[qi][d4+2] = v.z; Qs[qi][d4+3] = v.w;
    }
    const int q = t >> 3, dg = t & 7;
    float acc[16];
    #pragma unroll
    for (int i = 0; i < 16; i++) acc[i] = 0.f;
    float m = -1e30f, l = 0.f;
    const float sc = 0.08838834764831845f;  // 1/sqrt(128)
    const float* kbase = g_k + (size_t)(b * NKV + kv) * LTOT * HDD;
    const float* vbase = g_v + (size_t)(b * NKV + kv) * LTOT * HDD;
    __syncthreads();
    for (int k0 = 0; k0 < LTOT; k0 += 32) {
        for (int idx = t; idx < 1024; idx += 256) {
            int ki = idx >> 5, d4 = (idx & 31) << 2;
            float4 v = *(const float4*)(kbase + (size_t)(k0 + ki) * HDD + d4);
            KVs[ki][d4] = v.x; KVs[ki][d4+1] = v.y; KVs[ki][d4+2] = v.z; KVs[ki][d4+3] = v.w;
        }
        __syncthreads();
        {
            int kb = dg << 2;
            float s0 = 0.f, s1 = 0.f, s2 = 0.f, s3 = 0.f;
            #pragma unroll 4
            for (int d = 0; d < 128; d++) {
                float qv = Qs[q][d];
                s0 += qv * KVs[kb][d];
                s1 += qv * KVs[kb+1][d];
                s2 += qv * KVs[kb+2][d];
                s3 += qv * KVs[kb+3][d];
            }
            Ss[q][kb] = s0 * sc; Ss[q][kb+1] = s1 * sc;
            Ss[q][kb+2] = s2 * sc; Ss[q][kb+3] = s3 * sc;
        }
        __syncthreads();
        float srow[32];
        float rmax = -1e30f;
        #pragma unroll
        for (int k = 0; k < 32; k++) { srow[k] = Ss[q][k]; rmax = fmaxf(rmax, srow[k]); }
        for (int idx = t; idx < 1024; idx += 256) {
            int ki = idx >> 5, d4 = (idx & 31) << 2;
            float4 v = *(const float4*)(vbase + (size_t)(k0 + ki) * HDD + d4);
            KVs[ki][d4] = v.x; KVs[ki][d4+1] = v.y; KVs[ki][d4+2] = v.z; KVs[ki][d4+3] = v.w;
        }
        float newm = fmaxf(m, rmax);
        float corr = __expf(m - newm);
        float psum = 0.f;
        #pragma unroll
        for (int k = 0; k < 32; k++) { srow[k] = __expf(srow[k] - newm); psum += srow[k]; }
        l = l * corr + psum;
        m = newm;
        #pragma unroll
        for (int i = 0; i < 16; i++) acc[i] *= corr;
        __syncthreads();
        #pragma unroll
        for (int k = 0; k < 32; k++) {
            float p = srow[k];
            #pragma unroll
            for (int i = 0; i < 16; i++) acc[i] += p * KVs[k][dg + (i << 3)];
        }
        __syncthreads();
    }
    float inv = 1.f / l;
    float* op = g_attn + (size_t)(b * SEQ + q0 + q) * DIMM + h * HDD;
    #pragma unroll
    for (int i = 0; i < 16; i++) op[dg + (i << 3)] = acc[i] * inv;
}

// ------------------------- router ------------------------------------------
__global__ __launch_bounds__(1024) void tembdot_kernel(const float* __restrict__ temb,
                                                       const float* __restrict__ Wg) {
    int wid = threadIdx.x >> 5, lane = threadIdx.x & 31;
    int b = wid / NE, e = wid % NE;
    const float* t = temb + b * DIMM;
    const float* w = Wg + (size_t)e * 2 * DIMM;
    float acc = 0.f;
    for (int d = lane; d < DIMM; d += 32) acc += t[d] * w[d];
    #pragma unroll
    for (int o = 16; o; o >>= 1) acc += __shfl_xor_sync(0xffffffffu, acc, o);
    if (lane == 0) g_tembdot[wid] = acc;
}

__global__ __launch_bounds__(128) void router_kernel(const float* __restrict__ Wg) {
    __shared__ float lg[NE];
    int tokid = blockIdx.x;
    int b = tokid >> 10, s = tokid & 1023;
    int w = threadIdx.x >> 5, lane = threadIdx.x & 31;
    const float* x = g_normed2 + (size_t)tokid * DIMM;
    for (int e = w * 4; e < w * 4 + 4; e++) {
        const float* wg = Wg + (size_t)e * 2 * DIMM + DIMM;
        float acc = 0.f;
        for (int d = lane; d < DIMM; d += 32) acc += x[d] * wg[d];
        #pragma unroll
        for (int o = 16; o; o >>= 1) acc += __shfl_xor_sync(0xffffffffu, acc, o);
        if (lane == 0) lg[e] = acc + g_tembdot[b * NE + e];
    }
    __syncthreads();
    if (threadIdx.x == 0) {
        float mx = -1e30f;
        for (int e = 0; e < NE; e++) mx = fmaxf(mx, lg[e]);
        float ex[NE], sm = 0.f;
        for (int e = 0; e < NE; e++) { ex[e] = __expf(lg[e] - mx); sm += ex[e]; }
        float inv = 1.f / sm;
        for (int e = 0; e < NE; e++)
            g_aff[((size_t)(b * NE + e)) * SEQ + s] = ex[e] * inv;
    }
}

// ------------------------- exact top-k via bitonic sort ---------------------
__global__ __launch_bounds__(512) void topk_kernel() {
    __shared__ float v[1024];
    __shared__ int   id[1024];
    int be = blockIdx.x;
    const float* rowp = g_aff + (size_t)be * SEQ;
    int t = threadIdx.x;
    for (int i = t; i < 1024; i += 512) { v[i] = rowp[i]; id[i] = i; }
    __syncthreads();
    for (int k = 2; k <= 1024; k <<= 1) {
        for (int j = k >> 1; j > 0; j >>= 1) {
            for (int i = t; i < 1024; i += 512) {
                int ixj = i ^ j;
                if (ixj > i) {
                    bool up = ((i & k) == 0);
                    float va = v[i], vb = v[ixj];
                    int ia = id[i], ib = id[ixj];
                    bool a_first = (va > vb) || (va == vb && ia < ib);
                    bool sw = up ? !a_first : a_first;
                    if (sw) { v[i] = vb; v[ixj] = va; id[i] = ib; id[ixj] = ia; }
                }
            }
            __syncthreads();
        }
    }
    if (t < CAP) {
        g_gating[be * CAP + t] = v[t];
        g_topidx[be * CAP + t] = id[t];
    }
}

__global__ void zero_sums_kernel() {
    int i = blockIdx.x * blockDim.x + threadIdx.x;
    if (i < NTOK) g_sums[i] = 0.f;
}

__global__ void sum_acc_kernel() {
    int i = blockIdx.x * blockDim.x + threadIdx.x;
    if (i >= BSZ * NE * CAP) return;
    int be = i / CAP;
    int b = be / NE;
    int tok = b * SEQ + g_topidx[i];
    atomicAdd(&g_sums[tok], g_gating[i]);
}

__global__ void gate_norm_kernel() {
    int i = blockIdx.x * blockDim.x + threadIdx.x;
    if (i >= BSZ * NE * CAP) return;
    int c = i % CAP;
    int be = i / CAP;
    int b = be / NE, e = be % NE;
    int tok = b * SEQ + g_topidx[i];
    float g = g_gating[i] / (g_sums[tok] + 1e-12f) * 2.5f;
    int rowflat = (e * BSZ + b) * CAP + c;
    g_rowmap[rowflat] = tok;
    g_rscale[rowflat] = g;
}

// ------------------------- swiglu activation --------------------------------
__global__ __launch_bounds__(256) void swiglu_kernel(const float* __restrict__ h,
                                                     float* __restrict__ out) {
    int r = blockIdx.x;
    const float4* a = (const float4*)(h + (size_t)r * 2 * NI);
    const float4* g = (const float4*)(h + (size_t)r * 2 * NI + NI);
    float4* o = (float4*)(out + (size_t)r * NI);
    for (int i = threadIdx.x; i < NI / 4; i += 256) {
        float4 av = a[i], gv = g[i], ov;
        ov.x = av.x * (gv.x / (1.f + __expf(-gv.x)));
        ov.y = av.y * (gv.y / (1.f + __expf(-gv.y)));
        ov.z = av.z * (gv.z / (1.f + __expf(-gv.z)));
        ov.w = av.w * (gv.w / (1.f + __expf(-gv.w)));
        o[i] = ov;
    }
}

// ------------------------- final residual -----------------------------------
__global__ __launch_bounds__(256) void final_kernel(float* __restrict__ out) {
    int r = blockIdx.x;
    int b = r >> 10;
    const float4* hs = (const float4*)(g_hs1 + (size_t)r * DIMM);
    const float4* mo = (const float4*)(g_outflat + (size_t)r * DIMM);
    const float4* gg = (const float4*)(g_tg2 + (size_t)b * DIMM);
    float4* o = (float4*)(out + (size_t)r * DIMM);
    for (int i = threadIdx.x; i < DIMM / 4; i += 256) {
        float4 h = hs[i], m = mo[i], g = gg[i], v;
        v.x = h.x + g.x * m.x; v.y = h.y + g.y * m.y;
        v.z = h.z + g.z * m.z; v.w = h.w + g.w * m.w;
        o[i] = v;
    }
}

// ------------------------- launcher -----------------------------------------
extern "C" void kernel_launch(void* const* d_in, const int* in_sizes, int n_in,
                              void* d_out, int out_size) {
    const float* hidden = (const float*)d_in[0];
    const float* enc    = (const float*)d_in[1];
    const float* temb   = (const float*)d_in[2];
    const float* W_mod  = (const float*)d_in[3];
    const float* b_mod  = (const float*)d_in[4];
    const float* W_enc  = (const float*)d_in[5];
    const float* b_enc  = (const float*)d_in[6];
    const float* Wq     = (const float*)d_in[7];
    const float* Wk     = (const float*)d_in[8];
    const float* Wv     = (const float*)d_in[9];
    const float* Wak    = (const float*)d_in[10];
    const float* Wav    = (const float*)d_in[11];
    const float* nq_w   = (const float*)d_in[12];
    const float* nk_w   = (const float*)d_in[13];
    const float* nak_w  = (const float*)d_in[14];
    const float* Wo     = (const float*)d_in[15];
    const float* Wg     = (const float*)d_in[16];
    const float* We_in  = (const float*)d_in[17];
    const float* We_out = (const float*)d_in[18];
    const float* Ws_in  = (const float*)d_in[19];
    const float* Ws_out = (const float*)d_in[20];
    float* out = (float*)d_out;

    void* pv;
    cudaGetSymbolAddress(&pv, g_ctx);     float* p_ctx     = (float*)pv;
    cudaGetSymbolAddress(&pv, g_imgmod);  float* p_imgmod  = (float*)pv;
    cudaGetSymbolAddress(&pv, g_q);       float* p_q       = (float*)pv;
    cudaGetSymbolAddress(&pv, g_kimg);    float* p_kimg    = (float*)pv;
    cudaGetSymbolAddress(&pv, g_vimg);    float* p_vimg    = (float*)pv;
    cudaGetSymbolAddress(&pv, g_ktxt);    float* p_ktxt    = (float*)pv;
    cudaGetSymbolAddress(&pv, g_vtxt);    float* p_vtxt    = (float*)pv;
    cudaGetSymbolAddress(&pv, g_attn);    float* p_attn    = (float*)pv;
    cudaGetSymbolAddress(&pv, g_hs1);     float* p_hs1     = (float*)pv;
    cudaGetSymbolAddress(&pv, g_mod2);    float* p_mod2    = (float*)pv;
    cudaGetSymbolAddress(&pv, g_normed2); float* p_normed2 = (float*)pv;
    cudaGetSymbolAddress(&pv, g_hmoe);    float* p_hmoe    = (float*)pv;
    cudaGetSymbolAddress(&pv, g_actmoe);  float* p_actmoe  = (float*)pv;
    cudaGetSymbolAddress(&pv, g_hsh);     float* p_hsh     = (float*)pv;
    cudaGetSymbolAddress(&pv, g_actsh);   float* p_actsh   = (float*)pv;
    cudaGetSymbolAddress(&pv, g_outflat); float* p_outflat = (float*)pv;
    cudaGetSymbolAddress(&pv, g_scale1);  float* p_scale1  = (float*)pv;
    cudaGetSymbolAddress(&pv, g_scale2);  float* p_scale2  = (float*)pv;
    cudaGetSymbolAddress(&pv, g_tg1);     float* p_tg1     = (float*)pv;
    cudaGetSymbolAddress(&pv, g_rowmap);  int*   p_rowmap  = (int*)pv;
    cudaGetSymbolAddress(&pv, g_rscale);  float* p_rscale  = (float*)pv;

    cudaFuncSetAttribute(mma_gemm<0,false>, cudaFuncAttributeMaxDynamicSharedMemorySize, MMSM);
    cudaFuncSetAttribute(mma_gemm<1,false>, cudaFuncAttributeMaxDynamicSharedMemorySize, MMSM);
    cudaFuncSetAttribute(mma_gemm<2,false>, cudaFuncAttributeMaxDynamicSharedMemorySize, MMSM);
    cudaFuncSetAttribute(mma_gemm<3,false>, cudaFuncAttributeMaxDynamicSharedMemorySize, MMSM);
    cudaFuncSetAttribute(mma_gemm<0,true>,  cudaFuncAttributeMaxDynamicSharedMemorySize, MMSM);

    const float* NFP = nullptr;
    const int*   NIP = nullptr;

    // 1. modulation
    mod_kernel<<<1536, 256>>>(temb, W_mod, b_mod);
    // 2. context projection (+bias)
    mma_gemm<1,false><<<dim3(12, 8, 1), 256, MMSM>>>(enc, W_enc, p_ctx,
        BSZ*TXT, DIMM, JD, 0, 0, 0, b_enc, NFP, NFP, NIP, NFP, NIP);
    // 3. LN1 * scale1
    ln_mod_kernel<<<NTOK, 256>>>(hidden, p_scale1, p_imgmod, nullptr);
    // 4. projections
    mma_gemm<0,false><<<dim3(12, 16, 1), 256, MMSM>>>(p_imgmod, Wq, p_q,
        NTOK, DIMM, DIMM, 0, 0, 0, NFP, NFP, NFP, NIP, NFP, NIP);
    mma_gemm<0,false><<<dim3(4, 16, 1), 256, MMSM>>>(p_imgmod, Wk, p_kimg,
        NTOK, IKV, DIMM, 0, 0, 0, NFP, NFP, NFP, NIP, NFP, NIP);
    mma_gemm<0,false><<<dim3(4, 16, 1), 256, MMSM>>>(p_imgmod, Wv, p_vimg,
        NTOK, IKV, DIMM, 0, 0, 0, NFP, NFP, NFP, NIP, NFP, NIP);
    mma_gemm<0,false><<<dim3(4, 8, 1), 256, MMSM>>>(p_ctx, Wak, p_ktxt,
        BSZ*TXT, IKV, DIMM, 0, 0, 0, NFP, NFP, NFP, NIP, NFP, NIP);
    mma_gemm<0,false><<<dim3(4, 8, 1), 256, MMSM>>>(p_ctx, Wav, p_vtxt,
        BSZ*TXT, IKV, DIMM, 0, 0, 0, NFP, NFP, NFP, NIP, NFP, NIP);
    // 5. norms + repack
    rms_q_kernel<<<3072, 256>>>(nq_w);
    kv_repack_kernel<<<1536, 256>>>(nk_w, nak_w);
    // 6. attention
    flash_kernel<<<dim3(SEQ/32, NH, BSZ), 256>>>();
    // 7. output proj + gated residual
    mma_gemm<2,false><<<dim3(12, 16, 1), 256, MMSM>>>(p_attn, Wo, p_hs1,
        NTOK, DIMM, DIMM, 0, 0, 0, NFP, hidden, p_tg1, NIP, NFP, NIP);
    // 8. LN2
    ln_mod_kernel<<<NTOK, 256>>>(p_hs1, p_scale2, p_mod2, p_normed2);
    // 9. router
    tembdot_kernel<<<1, 1024>>>(temb, Wg);
    router_kernel<<<NTOK, 128>>>(Wg);
    topk_kernel<<<BSZ*NE, 512>>>();
    zero_sums_kernel<<<8, 256>>>();
    sum_acc_kernel<<<64, 256>>>();
    gate_norm_kernel<<<64, 256>>>();
    // 10. expert GEMM 1 (gathered A rows, batched over 16 experts)
    mma_gemm<0,true><<<dim3(21, 8, 16), 256, MMSM>>>(p_mod2, We_in, p_hmoe,
        BSZ*CAP, 2*NI, DIMM,
        0, (long long)2*NI*DIMM, (long long)BSZ*CAP*2*NI,
        NFP, NFP, NFP, NIP, NFP, p_rowmap);
    swiglu_kernel<<<MROWS, 256>>>(p_hmoe, p_actmoe);
    // 11. shared expert
    mma_gemm<0,false><<<dim3(21, 16, 1), 256, MMSM>>>(p_mod2, Ws_in, p_hsh,
        NTOK, 2*NI, DIMM, 0, 0, 0, NFP, NFP, NFP, NIP, NFP, NIP);
    swiglu_kernel<<<NTOK, 256>>>(p_hsh, p_actsh);
    mma_gemm<0,false><<<dim3(12, 16, 1), 256, MMSM>>>(p_actsh, Ws_out, p_outflat,
        NTOK, DIMM, NI, 0, 0, 0, NFP, NFP, NFP, NIP, NFP, NIP);
    // 12. expert GEMM 2 with atomic scatter onto shared output
    mma_gemm<3,false><<<dim3(12, 8, 16), 256, MMSM>>>(p_actmoe, We_out, p_outflat,
        BSZ*CAP, DIMM, NI,
        (long long)BSZ*CAP*NI, (long long)DIMM*NI, 0,
        NFP, NFP, NFP, p_rowmap, p_rscale, NIP);
    // 13. final gated residual
    final_kernel<<<NTOK, 256>>>(out);
}